// round 16
// baseline (speedup 1.0000x reference)
#include <cuda_runtime.h>
#include <cuda_fp16.h>
#include <cstdint>

// ---------------------------------------------------------------------------
// Problem constants
// ---------------------------------------------------------------------------
static constexpr int B_  = 8;
static constexpr int C_  = 256;
static constexpr int NL_ = 4;
static constexpr int NP_ = 4;
static constexpr int NLAYERS_ = 6;
static constexpr int FFN_ = 1024;
static constexpr int DH_ = 32;
static constexpr int Q_  = 64*64 + 32*32 + 16*16 + 8*8;   // 5440
static constexpr int M_  = B_ * Q_;                        // 43520
static constexpr int NCHUNK_ = 4;
static constexpr int MQ_ = M_ / NCHUNK_;                   // 10880 (2 batches)

// per-layer weight offsets inside the fp16-weight pool ([N][K] layout)
static constexpr size_t OFF_WV  = 0;
static constexpr size_t OFF_WSA = 65536;    // fused [Wsamp(256) ; Wattn(128)]
static constexpr size_t OFF_WO  = 163840;
static constexpr size_t OFF_W1  = 229376;
static constexpr size_t OFF_W2  = 491520;
static constexpr size_t W_LAYER = 753664;

__device__ __constant__ int c_lvl_h[4]     = {64, 32, 16, 8};
__device__ __constant__ int c_lvl_w[4]     = {64, 32, 16, 8};
__device__ __constant__ int c_lvl_start[4] = {0, 4096, 5120, 5376};

// ---------------------------------------------------------------------------
// Scratch (static device globals)
// ---------------------------------------------------------------------------
__device__ float  d_pos    [(size_t)M_ * C_];
__device__ float  d_offlog [(size_t)M_ * 384];    // fused offsets(256)+logits(128)
__device__ float  d_ref    [Q_ * 2];
__device__ float  d_bsa    [NLAYERS_ * 384];      // fused bias [bsamp ; battn]
__device__ __half d_valh[(size_t)M_ * C_];        // fp16 value (sampled tensor)
__device__ __half d_tmph[(size_t)M_ * C_];        // fp16 pre-LN branch output
__device__ __half d_xh[(size_t)M_ * C_];          // fp16 activations (GEMM A inputs)
__device__ __half d_qh[(size_t)M_ * C_];
__device__ __half d_ah[(size_t)M_ * C_];
__device__ __half d_hh[(size_t)M_ * FFN_];
__device__ __half d_wh[(size_t)NLAYERS_ * W_LAYER];   // fp16 weights [N][K]

// ---------------------------------------------------------------------------
// Helpers
// ---------------------------------------------------------------------------
__device__ __forceinline__ uint32_t smem_u32(const void* p) {
    uint32_t a;
    asm("{ .reg .u64 t; cvta.to.shared.u64 t, %1; cvt.u32.u64 %0, t; }"
        : "=r"(a) : "l"(p));
    return a;
}
#define CP16(dst, src) \
    asm volatile("cp.async.cg.shared.global [%0], [%1], 16;" :: "r"(dst), "l"(src))
#define CP_COMMIT() asm volatile("cp.async.commit_group;" ::: "memory")
#define CP_WAIT(n)  asm volatile("cp.async.wait_group %0;" :: "n"(n) : "memory")

__device__ __forceinline__ void ldsm4(uint32_t& r0, uint32_t& r1,
                                      uint32_t& r2, uint32_t& r3, uint32_t addr)
{
    asm volatile("ldmatrix.sync.aligned.m8n8.x4.shared.b16 {%0,%1,%2,%3}, [%4];"
                 : "=r"(r0), "=r"(r1), "=r"(r2), "=r"(r3) : "r"(addr));
}
__device__ __forceinline__ void mma16816(float* c, const uint32_t* a,
                                         const uint32_t* b)
{
    asm volatile(
        "mma.sync.aligned.m16n8k16.row.col.f32.f16.f16.f32 "
        "{%0,%1,%2,%3}, {%4,%5,%6,%7}, {%8,%9}, {%0,%1,%2,%3};\n"
        : "+f"(c[0]), "+f"(c[1]), "+f"(c[2]), "+f"(c[3])
        : "r"(a[0]), "r"(a[1]), "r"(a[2]), "r"(a[3]), "r"(b[0]), "r"(b[1]));
}

struct alignas(8) H4 { __half2 a, b; };
__device__ __forceinline__ H4 rn4(float a, float b, float c, float d)
{
    return H4{__halves2half2(__float2half_rn(a), __float2half_rn(b)),
              __halves2half2(__float2half_rn(c), __float2half_rn(d))};
}

// ---------------------------------------------------------------------------
// Setup kernels
// ---------------------------------------------------------------------------
__global__ void ref_kernel()
{
    int q = blockIdx.x * blockDim.x + threadIdx.x;
    if (q >= Q_) return;
    int lvl = (q < 4096) ? 0 : (q < 5120) ? 1 : (q < 5376) ? 2 : 3;
    int start = c_lvl_start[lvl];
    int w = c_lvl_w[lvl], h = c_lvl_h[lvl];
    int idx = q - start;
    int row = idx / w, col = idx - row * w;
    d_ref[q * 2 + 0] = (col + 0.5f) / (float)w;
    d_ref[q * 2 + 1] = (row + 0.5f) / (float)h;
}

__global__ void bias_pack_kernel(const float* __restrict__ bsamp,
                                 const float* __restrict__ battn)
{
    int i = blockIdx.x * blockDim.x + threadIdx.x;
    if (i >= NLAYERS_ * 384) return;
    int layer = i / 384, j = i % 384;
    d_bsa[i] = (j < 256) ? bsamp[layer * 256 + j] : battn[layer * 128 + (j - 256)];
}

// Vectorized init: pos = pos_flat + lvl_emb; x = src; xh = rn(src); qh = rn(src+pos)
__global__ void init_kernel(const float* __restrict__ src,
                            const float* __restrict__ pos_flat,
                            const float* __restrict__ level_embed,
                            float* __restrict__ x)
{
    size_t i4 = (size_t)blockIdx.x * blockDim.x + threadIdx.x;
    if (i4 >= (size_t)M_ * C_ / 4) return;
    const size_t base = i4 * 4;
    const int c4 = (int)(base & (C_ - 1));
    const int q  = (int)((base >> 8) % Q_);
    const int lvl = (q < 4096) ? 0 : (q < 5120) ? 1 : (q < 5376) ? 2 : 3;

    float4 pv = *(const float4*)&pos_flat[base];
    float4 le = *(const float4*)&level_embed[lvl * C_ + c4];
    pv.x += le.x; pv.y += le.y; pv.z += le.z; pv.w += le.w;
    *(float4*)&d_pos[base] = pv;

    float4 v = *(const float4*)&src[base];
    *(float4*)&x[base] = v;

    *(H4*)&d_xh[base] = rn4(v.x, v.y, v.z, v.w);
    *(H4*)&d_qh[base] = rn4(v.x + pv.x, v.y + pv.y, v.z + pv.z, v.w + pv.w);
}

// weight convert+transpose:  W (K,N) fp32 -> Wt[N][K] fp16
__global__ void wsplit_kernel(const float* __restrict__ Wval,
                              const float* __restrict__ Wsamp,
                              const float* __restrict__ Wattn,
                              const float* __restrict__ Wout,
                              const float* __restrict__ Wfc1,
                              const float* __restrict__ Wfc2)
{
    int bz = blockIdx.z;
    int layer = bz / 6, mat = bz % 6;
    const float* src; int K, N; size_t doff;
    switch (mat) {
        case 0: src = Wval  + (size_t)layer * 65536;  K = 256;  N = 256;  doff = OFF_WV; break;
        case 1: src = Wsamp + (size_t)layer * 65536;  K = 256;  N = 256;  doff = OFF_WSA; break;
        case 2: src = Wattn + (size_t)layer * 32768;  K = 256;  N = 128;  doff = OFF_WSA + 65536; break;
        case 3: src = Wout  + (size_t)layer * 65536;  K = 256;  N = 256;  doff = OFF_WO; break;
        case 4: src = Wfc1  + (size_t)layer * 262144; K = 256;  N = 1024; doff = OFF_W1; break;
        default:src = Wfc2  + (size_t)layer * 262144; K = 1024; N = 256;  doff = OFF_W2; break;
    }
    doff += (size_t)layer * W_LAYER;
    int bx = blockIdx.x, by = blockIdx.y;
    if (bx * 32 >= N || by * 32 >= K) return;

    __shared__ float tile[32][33];
    int tx = threadIdx.x, ty = threadIdx.y;   // 32 x 8
#pragma unroll
    for (int i = 0; i < 4; i++) {
        int k = by * 32 + ty + i * 8;
        tile[ty + i * 8][tx] = src[(size_t)k * N + bx * 32 + tx];
    }
    __syncthreads();
#pragma unroll
    for (int i = 0; i < 4; i++) {
        int n = bx * 32 + ty + i * 8;
        int k = by * 32 + tx;
        d_wh[doff + (size_t)n * K + k] = __float2half_rn(tile[tx][ty + i * 8]);
    }
}

// ---------------------------------------------------------------------------
// fp16 tensor GEMM:  D = act( Ah @ Bh^T + bias ).  A fp16, B fp16 [N][K].
// 3-stage cp.async, SW128 swizzle (128B rows). Tile 128x128x64.
// 128 thr = 4 warps (2M x 2N), warp tile 64x64.
// Stage: A(16K) + B(16K) = 32768; 3 stages = 98304 B.
// ---------------------------------------------------------------------------
static constexpr int ARR = 16384;
static constexpr int STG = 32768;

__device__ __forceinline__ void load_stage(uint32_t base,
    const __half* __restrict__ A0, const __half* __restrict__ B0,
    int bm, int bn, int K, int kt, int tid)
{
#pragma unroll
    for (int it = 0; it < 16; it++) {
        int i   = it * 128 + tid;
        int arr = i >> 10;            // 0..1
        int rem = i & 1023;
        int r   = rem >> 3;           // 0..127
        int c   = rem & 7;            // 0..7 (16B chunks in 128B row)
        const __half* g = (arr == 0) ? A0 + (size_t)(bm + r) * K + kt
                                     : B0 + (size_t)(bn + r) * K + kt;
        uint32_t dst = base + arr * ARR + r * 128 + ((c ^ (r & 7)) << 4);
        CP16(dst, (const char*)g + c * 16);
    }
}

// OUTF32: fp32 out (Cf). OUTH: fp16 out (Ch).
template<bool RELU, bool OUTF32, bool OUTH>
__global__ __launch_bounds__(128, 2)
void hgemm_kernel(const __half* __restrict__ Ahg, const __half* __restrict__ Bhg,
                  const float* __restrict__ bias,
                  float* __restrict__ Cf, __half* __restrict__ Ch,
                  int M, int N, int K)
{
    extern __shared__ char smem[];
    const uint32_t sb = smem_u32(smem);
    const int tid  = threadIdx.x;
    const int warp = tid >> 5, lane = tid & 31;
    const int bm = blockIdx.y * 128, bn = blockIdx.x * 128;
    const int wm = (warp >> 1) * 64;      // warp row base (0/64)
    const int wn = (warp & 1) * 64;       // warp col base (0/64)

    float acc[4][8][4];
#pragma unroll
    for (int i = 0; i < 4; i++)
#pragma unroll
        for (int j = 0; j < 8; j++)
#pragma unroll
            for (int r = 0; r < 4; r++) acc[i][j][r] = 0.f;

    const int a_row = (lane & 7) + ((lane >> 3) & 1) * 8;
    const int a_ch  = (lane >> 4) & 1;
    const int b_row = (lane & 7) + ((lane >> 4) & 1) * 8;
    const int b_ch  = (lane >> 3) & 1;

    const int T = K >> 6;   // BK = 64

    load_stage(sb,       Ahg, Bhg, bm, bn, K, 0,  tid);
    CP_COMMIT();
    load_stage(sb + STG, Ahg, Bhg, bm, bn, K, 64, tid);
    CP_COMMIT();

    uint32_t st = sb;
    for (int t = 0; t < T; t++) {
        CP_WAIT(1);
        __syncthreads();

        if (t + 2 < T) {
            uint32_t nxt = sb + (uint32_t)((t + 2) % 3) * STG;
            load_stage(nxt, Ahg, Bhg, bm, bn, K, (t + 2) * 64, tid);
        }
        CP_COMMIT();

#pragma unroll
        for (int ks = 0; ks < 4; ks++) {
            const int cb = ks * 2;    // 16B-chunk base of this k16 step
            uint32_t bh[8][2];
#pragma unroll
            for (int np = 0; np < 4; np++) {
                int r = wn + np * 16 + b_row;
                uint32_t addr = st + ARR + r * 128 +
                    (uint32_t)(((cb + b_ch) ^ (r & 7)) << 4);
                ldsm4(bh[2*np][0], bh[2*np][1], bh[2*np+1][0], bh[2*np+1][1], addr);
            }
#pragma unroll
            for (int mt = 0; mt < 4; mt++) {
                int r = wm + mt * 16 + a_row;
                uint32_t addr = st + r * 128 +
                    (uint32_t)(((cb + a_ch) ^ (r & 7)) << 4);
                uint32_t aH[4];
                ldsm4(aH[0], aH[1], aH[2], aH[3], addr);
#pragma unroll
                for (int nt = 0; nt < 8; nt++)
                    mma16816(acc[mt][nt], aH, bh[nt]);
            }
        }
        st = sb + (uint32_t)((t + 1) % 3) * STG;
    }

    const int g  = lane >> 2;
    const int tq = lane & 3;
#pragma unroll
    for (int mt = 0; mt < 4; mt++) {
        const int r0 = bm + wm + mt * 16 + g;
#pragma unroll
        for (int nt = 0; nt < 8; nt++) {
            const int c0 = bn + wn + nt * 8 + tq * 2;
            float2 bv = *(const float2*)&bias[c0];
            float o0 = acc[mt][nt][0] + bv.x;
            float o1 = acc[mt][nt][1] + bv.y;
            float o2 = acc[mt][nt][2] + bv.x;
            float o3 = acc[mt][nt][3] + bv.y;
            if (RELU) {
                o0 = fmaxf(o0, 0.f); o1 = fmaxf(o1, 0.f);
                o2 = fmaxf(o2, 0.f); o3 = fmaxf(o3, 0.f);
            }
            if (OUTF32) {
                *(float2*)&Cf[(size_t)r0 * N + c0]       = make_float2(o0, o1);
                *(float2*)&Cf[(size_t)(r0 + 8) * N + c0] = make_float2(o2, o3);
            }
            if (OUTH) {
                *(__half2*)&Ch[(size_t)r0 * N + c0] =
                    __halves2half2(__float2half_rn(o0), __float2half_rn(o1));
                *(__half2*)&Ch[(size_t)(r0 + 8) * N + c0] =
                    __halves2half2(__float2half_rn(o2), __float2half_rn(o3));
            }
        }
    }
}

// ---------------------------------------------------------------------------
// Deformable attention sampling (fp16 value gathers, fp32 math) -> fp16 out.
// row0: global row offset of this launch's first (b,q).
// ---------------------------------------------------------------------------
__global__ __launch_bounds__(256)
void deform_kernel(const __half* __restrict__ value,
                   const float* __restrict__ offlog, int row0)
{
    const int bq   = row0 + blockIdx.x;
    const int q    = bq % Q_;
    const int b    = bq / Q_;
    const int h    = threadIdx.x >> 5;
    const int lane = threadIdx.x & 31;
    const unsigned FULL = 0xFFFFFFFFu;

    float logit = offlog[(size_t)bq * 384 + 256 + h * 16 + (lane & 15)];
    float mx = logit;
#pragma unroll
    for (int s = 8; s; s >>= 1) mx = fmaxf(mx, __shfl_xor_sync(FULL, mx, s));
    float e = expf(logit - mx);
    float sm = e;
#pragma unroll
    for (int s = 8; s; s >>= 1) sm += __shfl_xor_sync(FULL, sm, s);
    float aw = e / sm;

    float offv = offlog[(size_t)bq * 384 + h * 32 + lane];
    const float rx = d_ref[q * 2 + 0];
    const float ry = d_ref[q * 2 + 1];

    float acc = 0.f;
    const __half* vb = value + (size_t)b * Q_ * C_ + h * DH_ + lane;

#pragma unroll
    for (int l = 0; l < NL_; l++) {
        const int   W  = c_lvl_w[l], H = c_lvl_h[l], st = c_lvl_start[l];
        const float fw = (float)W, fh = (float)H;
        const float iw = 1.f / fw, ih = 1.f / fh;
#pragma unroll
        for (int p = 0; p < NP_; p++) {
            const int j = l * NP_ + p;
            float ox  = __shfl_sync(FULL, offv, 2 * j);
            float oy  = __shfl_sync(FULL, offv, 2 * j + 1);
            float wj  = __shfl_sync(FULL, aw,   j);

            float x = (rx + ox * iw) * fw - 0.5f;
            float y = (ry + oy * ih) * fh - 0.5f;
            float x0f = floorf(x), y0f = floorf(y);
            int   x0  = (int)x0f,  y0  = (int)y0f;
            float fx = x - x0f, fy = y - y0f;
            float s = 0.f;

            bool vx0 = (x0 >= 0)     && (x0 < W);
            bool vx1 = (x0 + 1 >= 0) && (x0 + 1 < W);
            if (y0 >= 0 && y0 < H) {
                const __half* rp = vb + (size_t)(st + y0 * W) * C_;
                float wy = 1.f - fy;
                if (vx0) s += wy * (1.f - fx) * __half2float(rp[(size_t)x0 * C_]);
                if (vx1) s += wy * fx         * __half2float(rp[(size_t)(x0 + 1) * C_]);
            }
            if (y0 + 1 >= 0 && y0 + 1 < H) {
                const __half* rp = vb + (size_t)(st + (y0 + 1) * W) * C_;
                if (vx0) s += fy * (1.f - fx) * __half2float(rp[(size_t)x0 * C_]);
                if (vx1) s += fy * fx         * __half2float(rp[(size_t)(x0 + 1) * C_]);
            }
            acc = fmaf(wj, s, acc);
        }
    }
    d_ah[(size_t)bq * C_ + h * DH_ + lane] = __float2half_rn(acc);
}

// ---------------------------------------------------------------------------
// Fused residual-add + LayerNorm (vectorized): 4 rows per 256-thread block,
// 64 threads/row, float4/H4 per thread. y is fp16. row0 = global row offset.
// ---------------------------------------------------------------------------
template<bool WRITE_Q>
__global__ __launch_bounds__(256)
void add_ln_kernel(float* __restrict__ x, const __half* __restrict__ y,
                   const float* __restrict__ g, const float* __restrict__ b,
                   int row0)
{
    const int sub = threadIdx.x >> 6;          // row within block (0..3)
    const int t   = threadIdx.x & 63;          // 0..63
    const int row = row0 + blockIdx.x * 4 + sub;
    const size_t base = (size_t)row * C_ + t * 4;
    const unsigned FULL = 0xFFFFFFFFu;

    float4 xv = *(const float4*)&x[base];
    H4 yh = *(const H4*)&y[base];
    float2 y0 = __half22float2(yh.a);
    float2 y1 = __half22float2(yh.b);
    float4 v  = make_float4(xv.x + y0.x, xv.y + y0.y, xv.z + y1.x, xv.w + y1.y);

    float s1 = v.x + v.y + v.z + v.w;
    float s2 = v.x * v.x + v.y * v.y + v.z * v.z + v.w * v.w;
#pragma unroll
    for (int o = 16; o; o >>= 1) {
        s1 += __shfl_xor_sync(FULL, s1, o);
        s2 += __shfl_xor_sync(FULL, s2, o);
    }
    __shared__ float sh1[8], sh2[8];
    const int w = threadIdx.x >> 5, lane = threadIdx.x & 31;
    if (lane == 0) { sh1[w] = s1; sh2[w] = s2; }
    __syncthreads();
    float tot1 = sh1[2 * sub] + sh1[2 * sub + 1];
    float tot2 = sh2[2 * sub] + sh2[2 * sub + 1];
    float mean = tot1 * (1.f / C_);
    float var  = tot2 * (1.f / C_) - mean * mean;
    float rs   = rsqrtf(var + 1e-5f);

    float4 gg = *(const float4*)&g[t * 4];
    float4 bb = *(const float4*)&b[t * 4];
    float4 o;
    o.x = (v.x - mean) * rs * gg.x + bb.x;
    o.y = (v.y - mean) * rs * gg.y + bb.y;
    o.z = (v.z - mean) * rs * gg.z + bb.z;
    o.w = (v.w - mean) * rs * gg.w + bb.w;
    *(float4*)&x[base] = o;

    *(H4*)&d_xh[base] = rn4(o.x, o.y, o.z, o.w);
    if (WRITE_Q) {
        float4 pv = *(const float4*)&d_pos[base];
        *(H4*)&d_qh[base] = rn4(o.x + pv.x, o.y + pv.y, o.z + pv.z, o.w + pv.w);
    }
}

// ---------------------------------------------------------------------------
// Launch
// ---------------------------------------------------------------------------
extern "C" void kernel_launch(void* const* d_in, const int* in_sizes, int n_in,
                              void* d_out, int out_size)
{
    const float* src   = (const float*)d_in[0];
    const float* posf  = (const float*)d_in[1];
    const float* lemb  = (const float*)d_in[2];
    const float* Wsamp = (const float*)d_in[3];
    const float* bsamp = (const float*)d_in[4];
    const float* Wattn = (const float*)d_in[5];
    const float* battn = (const float*)d_in[6];
    const float* Wval  = (const float*)d_in[7];
    const float* bval  = (const float*)d_in[8];
    const float* Wout  = (const float*)d_in[9];
    const float* bout  = (const float*)d_in[10];
    const float* g1    = (const float*)d_in[11];
    const float* b1    = (const float*)d_in[12];
    const float* Wfc1  = (const float*)d_in[13];
    const float* bfc1  = (const float*)d_in[14];
    const float* Wfc2  = (const float*)d_in[15];
    const float* bfc2  = (const float*)d_in[16];
    const float* g2    = (const float*)d_in[17];
    const float* b2    = (const float*)d_in[18];

    float* x = (float*)d_out;

    // aux streams + events (created once; host-side only)
    static cudaStream_t s_aux[NCHUNK_ - 1] = {};
    static cudaEvent_t  ev_fork = nullptr;
    static cudaEvent_t  ev_join[NCHUNK_ - 1] = {};
    if (s_aux[0] == nullptr) {
        for (int i = 0; i < NCHUNK_ - 1; i++) {
            cudaStreamCreateWithFlags(&s_aux[i], cudaStreamNonBlocking);
            cudaEventCreateWithFlags(&ev_join[i], cudaEventDisableTiming);
        }
        cudaEventCreateWithFlags(&ev_fork, cudaEventDisableTiming);
    }

    static const int SMEM_DYN = 98304;   // 3 stages x 32768
    cudaFuncSetAttribute(hgemm_kernel<false, true,  false>,
                         cudaFuncAttributeMaxDynamicSharedMemorySize, SMEM_DYN);
    cudaFuncSetAttribute(hgemm_kernel<false, false, true>,
                         cudaFuncAttributeMaxDynamicSharedMemorySize, SMEM_DYN);
    cudaFuncSetAttribute(hgemm_kernel<true,  false, true>,
                         cudaFuncAttributeMaxDynamicSharedMemorySize, SMEM_DYN);

    float *p_ol, *p_bsa;
    __half *p_vh, *p_tmph, *p_xh, *p_qh, *p_ah, *p_hh, *p_wh;
    cudaGetSymbolAddress((void**)&p_ol,   d_offlog);
    cudaGetSymbolAddress((void**)&p_bsa,  d_bsa);
    cudaGetSymbolAddress((void**)&p_vh,   d_valh);
    cudaGetSymbolAddress((void**)&p_tmph, d_tmph);
    cudaGetSymbolAddress((void**)&p_xh, d_xh);
    cudaGetSymbolAddress((void**)&p_qh, d_qh);
    cudaGetSymbolAddress((void**)&p_ah, d_ah);
    cudaGetSymbolAddress((void**)&p_hh, d_hh);
    cudaGetSymbolAddress((void**)&p_wh, d_wh);

    {
        size_t n4 = (size_t)M_ * C_ / 4;
        // setup fork: wsplit on s_aux[0], rest on main
        cudaEventRecord(ev_fork, 0);
        cudaStreamWaitEvent(s_aux[0], ev_fork, 0);
        wsplit_kernel<<<dim3(32, 32, 36), dim3(32, 8), 0, s_aux[0]>>>(
            Wval, Wsamp, Wattn, Wout, Wfc1, Wfc2);
        ref_kernel<<<(Q_ + 255) / 256, 256>>>();
        bias_pack_kernel<<<(NLAYERS_ * 384 + 255) / 256, 256>>>(bsamp, battn);
        init_kernel<<<(unsigned)((n4 + 255) / 256), 256>>>(src, posf, lemb, x);
    }

    // main must also wait for wsplit (weights used by all chains)
    cudaEventRecord(ev_join[0], s_aux[0]);
    cudaStreamWaitEvent(0, ev_join[0], 0);
    // fork NCHUNK_ independent batch-pair chains
    cudaEventRecord(ev_fork, 0);
    for (int i = 0; i < NCHUNK_ - 1; i++)
        cudaStreamWaitEvent(s_aux[i], ev_fork, 0);

    const int TILES = MQ_ / 128;              // 85
    const dim3 gN256(2, TILES);
    const dim3 gN384(3, TILES);
    const dim3 gN1024(8, TILES);

    for (int ch = 0; ch < NCHUNK_; ch++) {
        cudaStream_t st = (ch == 0) ? (cudaStream_t)0 : s_aux[ch - 1];
        const int r0 = ch * MQ_;

        for (int i = 0; i < NLAYERS_; i++) {
            const size_t wb = (size_t)i * W_LAYER;

            // value = fp16( x @ Wv + bv )
            hgemm_kernel<false, false, true><<<gN256, 128, SMEM_DYN, st>>>(
                p_xh + (size_t)r0 * 256, p_wh + wb + OFF_WV,
                bval + i * C_, nullptr, p_vh + (size_t)r0 * 256,
                MQ_, 256, 256);
            // [off | logits] = q @ [Ws ; Wa] + [bs ; ba]
            hgemm_kernel<false, true, false><<<gN384, 128, SMEM_DYN, st>>>(
                p_qh + (size_t)r0 * 256, p_wh + wb + OFF_WSA,
                p_bsa + i * 384, p_ol + (size_t)r0 * 384, nullptr,
                MQ_, 384, 256);
            // deformable sampling (fp16 value) -> ah (fp16)
            deform_kernel<<<MQ_, 256, 0, st>>>(p_vh, p_ol, r0);
            // attn = samp @ Wo + bo -> tmph (fp16)
            hgemm_kernel<false, false, true><<<gN256, 128, SMEM_DYN, st>>>(
                p_ah + (size_t)r0 * 256, p_wh + wb + OFF_WO,
                bout + i * C_, nullptr, p_tmph + (size_t)r0 * 256,
                MQ_, 256, 256);
            // x = LN(x + attn)
            add_ln_kernel<false><<<MQ_ / 4, 256, 0, st>>>(
                x, p_tmph, g1 + i * C_, b1 + i * C_, r0);
            // hid = relu(x @ W1 + b1) -> hh (fp16)
            hgemm_kernel<true, false, true><<<gN1024, 128, SMEM_DYN, st>>>(
                p_xh + (size_t)r0 * 256, p_wh + wb + OFF_W1,
                bfc1 + i * FFN_, nullptr, p_hh + (size_t)r0 * 1024,
                MQ_, 1024, 256);
            // tmp = hid @ W2 + b2 -> tmph (fp16)
            hgemm_kernel<false, false, true><<<gN256, 128, SMEM_DYN, st>>>(
                p_hh + (size_t)r0 * 1024, p_wh + wb + OFF_W2,
                bfc2 + i * C_, nullptr, p_tmph + (size_t)r0 * 256,
                MQ_, 256, 1024);
            // x = LN(x + ffn), also produce next-layer query fp16
            add_ln_kernel<true><<<MQ_ / 4, 256, 0, st>>>(
                x, p_tmph, g2 + i * C_, b2 + i * C_, r0);
        }
    }

    // join aux chains back into the capture stream
    for (int i = 0; i < NCHUNK_ - 1; i++) {
        cudaEventRecord(ev_join[i], s_aux[i]);
        cudaStreamWaitEvent(0, ev_join[i], 0);
    }
}

// round 17
// speedup vs baseline: 1.0220x; 1.0220x over previous
#include <cuda_runtime.h>
#include <cuda_fp16.h>
#include <cstdint>

// ---------------------------------------------------------------------------
// Problem constants
// ---------------------------------------------------------------------------
static constexpr int B_  = 8;
static constexpr int C_  = 256;
static constexpr int NL_ = 4;
static constexpr int NP_ = 4;
static constexpr int NLAYERS_ = 6;
static constexpr int FFN_ = 1024;
static constexpr int DH_ = 32;
static constexpr int Q_  = 64*64 + 32*32 + 16*16 + 8*8;   // 5440
static constexpr int M_  = B_ * Q_;                        // 43520
static constexpr int NCHUNK_ = 4;
static constexpr int MQ_ = M_ / NCHUNK_;                   // 10880 (2 batches)

// per-layer weight offsets inside the fp16-weight pool ([N][K] layout)
static constexpr size_t OFF_WV  = 0;
static constexpr size_t OFF_WSA = 65536;    // fused [Wsamp(256) ; Wattn(128)]
static constexpr size_t OFF_WO  = 163840;
static constexpr size_t OFF_W1  = 229376;
static constexpr size_t OFF_W2  = 491520;
static constexpr size_t W_LAYER = 753664;

__device__ __constant__ int c_lvl_h[4]     = {64, 32, 16, 8};
__device__ __constant__ int c_lvl_w[4]     = {64, 32, 16, 8};
__device__ __constant__ int c_lvl_start[4] = {0, 4096, 5120, 5376};

// ---------------------------------------------------------------------------
// Scratch (static device globals)
// ---------------------------------------------------------------------------
__device__ float  d_pos    [(size_t)M_ * C_];
__device__ float  d_value  [(size_t)M_ * C_];     // fp32 value (round 9/16: keep!)
__device__ float  d_ref    [Q_ * 2];
__device__ float  d_bsa    [NLAYERS_ * 384];      // fused bias [bsamp ; battn]
__device__ __half d_offlog[(size_t)M_ * 384];     // fp16 offsets(256)+logits(128)
__device__ __half d_tmph[(size_t)M_ * C_];        // fp16 pre-LN branch output
__device__ __half d_xh[(size_t)M_ * C_];          // fp16 activations (GEMM A inputs)
__device__ __half d_qh[(size_t)M_ * C_];
__device__ __half d_ah[(size_t)M_ * C_];
__device__ __half d_hh[(size_t)M_ * FFN_];
__device__ __half d_wh[(size_t)NLAYERS_ * W_LAYER];   // fp16 weights [N][K]

// ---------------------------------------------------------------------------
// Helpers
// ---------------------------------------------------------------------------
__device__ __forceinline__ uint32_t smem_u32(const void* p) {
    uint32_t a;
    asm("{ .reg .u64 t; cvta.to.shared.u64 t, %1; cvt.u32.u64 %0, t; }"
        : "=r"(a) : "l"(p));
    return a;
}
#define CP16(dst, src) \
    asm volatile("cp.async.cg.shared.global [%0], [%1], 16;" :: "r"(dst), "l"(src))
#define CP_COMMIT() asm volatile("cp.async.commit_group;" ::: "memory")
#define CP_WAIT(n)  asm volatile("cp.async.wait_group %0;" :: "n"(n) : "memory")

__device__ __forceinline__ void ldsm4(uint32_t& r0, uint32_t& r1,
                                      uint32_t& r2, uint32_t& r3, uint32_t addr)
{
    asm volatile("ldmatrix.sync.aligned.m8n8.x4.shared.b16 {%0,%1,%2,%3}, [%4];"
                 : "=r"(r0), "=r"(r1), "=r"(r2), "=r"(r3) : "r"(addr));
}
__device__ __forceinline__ void mma16816(float* c, const uint32_t* a,
                                         const uint32_t* b)
{
    asm volatile(
        "mma.sync.aligned.m16n8k16.row.col.f32.f16.f16.f32 "
        "{%0,%1,%2,%3}, {%4,%5,%6,%7}, {%8,%9}, {%0,%1,%2,%3};\n"
        : "+f"(c[0]), "+f"(c[1]), "+f"(c[2]), "+f"(c[3])
        : "r"(a[0]), "r"(a[1]), "r"(a[2]), "r"(a[3]), "r"(b[0]), "r"(b[1]));
}

struct alignas(8) H4 { __half2 a, b; };
__device__ __forceinline__ H4 rn4(float a, float b, float c, float d)
{
    return H4{__halves2half2(__float2half_rn(a), __float2half_rn(b)),
              __halves2half2(__float2half_rn(c), __float2half_rn(d))};
}

// ---------------------------------------------------------------------------
// Setup kernels
// ---------------------------------------------------------------------------
__global__ void ref_kernel()
{
    int q = blockIdx.x * blockDim.x + threadIdx.x;
    if (q >= Q_) return;
    int lvl = (q < 4096) ? 0 : (q < 5120) ? 1 : (q < 5376) ? 2 : 3;
    int start = c_lvl_start[lvl];
    int w = c_lvl_w[lvl], h = c_lvl_h[lvl];
    int idx = q - start;
    int row = idx / w, col = idx - row * w;
    d_ref[q * 2 + 0] = (col + 0.5f) / (float)w;
    d_ref[q * 2 + 1] = (row + 0.5f) / (float)h;
}

__global__ void bias_pack_kernel(const float* __restrict__ bsamp,
                                 const float* __restrict__ battn)
{
    int i = blockIdx.x * blockDim.x + threadIdx.x;
    if (i >= NLAYERS_ * 384) return;
    int layer = i / 384, j = i % 384;
    d_bsa[i] = (j < 256) ? bsamp[layer * 256 + j] : battn[layer * 128 + (j - 256)];
}

// Vectorized init: pos = pos_flat + lvl_emb; x = src; xh = rn(src); qh = rn(src+pos)
__global__ void init_kernel(const float* __restrict__ src,
                            const float* __restrict__ pos_flat,
                            const float* __restrict__ level_embed,
                            float* __restrict__ x)
{
    size_t i4 = (size_t)blockIdx.x * blockDim.x + threadIdx.x;
    if (i4 >= (size_t)M_ * C_ / 4) return;
    const size_t base = i4 * 4;
    const int c4 = (int)(base & (C_ - 1));
    const int q  = (int)((base >> 8) % Q_);
    const int lvl = (q < 4096) ? 0 : (q < 5120) ? 1 : (q < 5376) ? 2 : 3;

    float4 pv = *(const float4*)&pos_flat[base];
    float4 le = *(const float4*)&level_embed[lvl * C_ + c4];
    pv.x += le.x; pv.y += le.y; pv.z += le.z; pv.w += le.w;
    *(float4*)&d_pos[base] = pv;

    float4 v = *(const float4*)&src[base];
    *(float4*)&x[base] = v;

    *(H4*)&d_xh[base] = rn4(v.x, v.y, v.z, v.w);
    *(H4*)&d_qh[base] = rn4(v.x + pv.x, v.y + pv.y, v.z + pv.z, v.w + pv.w);
}

// weight convert+transpose:  W (K,N) fp32 -> Wt[N][K] fp16
__global__ void wsplit_kernel(const float* __restrict__ Wval,
                              const float* __restrict__ Wsamp,
                              const float* __restrict__ Wattn,
                              const float* __restrict__ Wout,
                              const float* __restrict__ Wfc1,
                              const float* __restrict__ Wfc2)
{
    int bz = blockIdx.z;
    int layer = bz / 6, mat = bz % 6;
    const float* src; int K, N; size_t doff;
    switch (mat) {
        case 0: src = Wval  + (size_t)layer * 65536;  K = 256;  N = 256;  doff = OFF_WV; break;
        case 1: src = Wsamp + (size_t)layer * 65536;  K = 256;  N = 256;  doff = OFF_WSA; break;
        case 2: src = Wattn + (size_t)layer * 32768;  K = 256;  N = 128;  doff = OFF_WSA + 65536; break;
        case 3: src = Wout  + (size_t)layer * 65536;  K = 256;  N = 256;  doff = OFF_WO; break;
        case 4: src = Wfc1  + (size_t)layer * 262144; K = 256;  N = 1024; doff = OFF_W1; break;
        default:src = Wfc2  + (size_t)layer * 262144; K = 1024; N = 256;  doff = OFF_W2; break;
    }
    doff += (size_t)layer * W_LAYER;
    int bx = blockIdx.x, by = blockIdx.y;
    if (bx * 32 >= N || by * 32 >= K) return;

    __shared__ float tile[32][33];
    int tx = threadIdx.x, ty = threadIdx.y;   // 32 x 8
#pragma unroll
    for (int i = 0; i < 4; i++) {
        int k = by * 32 + ty + i * 8;
        tile[ty + i * 8][tx] = src[(size_t)k * N + bx * 32 + tx];
    }
    __syncthreads();
#pragma unroll
    for (int i = 0; i < 4; i++) {
        int n = bx * 32 + ty + i * 8;
        int k = by * 32 + tx;
        d_wh[doff + (size_t)n * K + k] = __float2half_rn(tile[tx][ty + i * 8]);
    }
}

// ---------------------------------------------------------------------------
// fp16 tensor GEMM:  D = act( Ah @ Bh^T + bias ).  A fp16, B fp16 [N][K].
// 3-stage cp.async, SW128 swizzle (128B rows). Tile 128x128x64.
// 128 thr = 4 warps (2M x 2N), warp tile 64x64.
// Stage: A(16K) + B(16K) = 32768; 3 stages = 98304 B.
// ---------------------------------------------------------------------------
static constexpr int ARR = 16384;
static constexpr int STG = 32768;

__device__ __forceinline__ void load_stage(uint32_t base,
    const __half* __restrict__ A0, const __half* __restrict__ B0,
    int bm, int bn, int K, int kt, int tid)
{
#pragma unroll
    for (int it = 0; it < 16; it++) {
        int i   = it * 128 + tid;
        int arr = i >> 10;            // 0..1
        int rem = i & 1023;
        int r   = rem >> 3;           // 0..127
        int c   = rem & 7;            // 0..7 (16B chunks in 128B row)
        const __half* g = (arr == 0) ? A0 + (size_t)(bm + r) * K + kt
                                     : B0 + (size_t)(bn + r) * K + kt;
        uint32_t dst = base + arr * ARR + r * 128 + ((c ^ (r & 7)) << 4);
        CP16(dst, (const char*)g + c * 16);
    }
}

// OUTF32: fp32 out (Cf). OUTH: fp16 out (Ch).
template<bool RELU, bool OUTF32, bool OUTH>
__global__ __launch_bounds__(128, 2)
void hgemm_kernel(const __half* __restrict__ Ahg, const __half* __restrict__ Bhg,
                  const float* __restrict__ bias,
                  float* __restrict__ Cf, __half* __restrict__ Ch,
                  int M, int N, int K)
{
    extern __shared__ char smem[];
    const uint32_t sb = smem_u32(smem);
    const int tid  = threadIdx.x;
    const int warp = tid >> 5, lane = tid & 31;
    const int bm = blockIdx.y * 128, bn = blockIdx.x * 128;
    const int wm = (warp >> 1) * 64;      // warp row base (0/64)
    const int wn = (warp & 1) * 64;       // warp col base (0/64)

    float acc[4][8][4];
#pragma unroll
    for (int i = 0; i < 4; i++)
#pragma unroll
        for (int j = 0; j < 8; j++)
#pragma unroll
            for (int r = 0; r < 4; r++) acc[i][j][r] = 0.f;

    const int a_row = (lane & 7) + ((lane >> 3) & 1) * 8;
    const int a_ch  = (lane >> 4) & 1;
    const int b_row = (lane & 7) + ((lane >> 4) & 1) * 8;
    const int b_ch  = (lane >> 3) & 1;

    const int T = K >> 6;   // BK = 64

    load_stage(sb,       Ahg, Bhg, bm, bn, K, 0,  tid);
    CP_COMMIT();
    load_stage(sb + STG, Ahg, Bhg, bm, bn, K, 64, tid);
    CP_COMMIT();

    uint32_t st = sb;
    for (int t = 0; t < T; t++) {
        CP_WAIT(1);
        __syncthreads();

        if (t + 2 < T) {
            uint32_t nxt = sb + (uint32_t)((t + 2) % 3) * STG;
            load_stage(nxt, Ahg, Bhg, bm, bn, K, (t + 2) * 64, tid);
        }
        CP_COMMIT();

#pragma unroll
        for (int ks = 0; ks < 4; ks++) {
            const int cb = ks * 2;    // 16B-chunk base of this k16 step
            uint32_t bh[8][2];
#pragma unroll
            for (int np = 0; np < 4; np++) {
                int r = wn + np * 16 + b_row;
                uint32_t addr = st + ARR + r * 128 +
                    (uint32_t)(((cb + b_ch) ^ (r & 7)) << 4);
                ldsm4(bh[2*np][0], bh[2*np][1], bh[2*np+1][0], bh[2*np+1][1], addr);
            }
#pragma unroll
            for (int mt = 0; mt < 4; mt++) {
                int r = wm + mt * 16 + a_row;
                uint32_t addr = st + r * 128 +
                    (uint32_t)(((cb + a_ch) ^ (r & 7)) << 4);
                uint32_t aH[4];
                ldsm4(aH[0], aH[1], aH[2], aH[3], addr);
#pragma unroll
                for (int nt = 0; nt < 8; nt++)
                    mma16816(acc[mt][nt], aH, bh[nt]);
            }
        }
        st = sb + (uint32_t)((t + 1) % 3) * STG;
    }

    const int g  = lane >> 2;
    const int tq = lane & 3;
#pragma unroll
    for (int mt = 0; mt < 4; mt++) {
        const int r0 = bm + wm + mt * 16 + g;
#pragma unroll
        for (int nt = 0; nt < 8; nt++) {
            const int c0 = bn + wn + nt * 8 + tq * 2;
            float2 bv = *(const float2*)&bias[c0];
            float o0 = acc[mt][nt][0] + bv.x;
            float o1 = acc[mt][nt][1] + bv.y;
            float o2 = acc[mt][nt][2] + bv.x;
            float o3 = acc[mt][nt][3] + bv.y;
            if (RELU) {
                o0 = fmaxf(o0, 0.f); o1 = fmaxf(o1, 0.f);
                o2 = fmaxf(o2, 0.f); o3 = fmaxf(o3, 0.f);
            }
            if (OUTF32) {
                *(float2*)&Cf[(size_t)r0 * N + c0]       = make_float2(o0, o1);
                *(float2*)&Cf[(size_t)(r0 + 8) * N + c0] = make_float2(o2, o3);
            }
            if (OUTH) {
                *(__half2*)&Ch[(size_t)r0 * N + c0] =
                    __halves2half2(__float2half_rn(o0), __float2half_rn(o1));
                *(__half2*)&Ch[(size_t)(r0 + 8) * N + c0] =
                    __halves2half2(__float2half_rn(o2), __float2half_rn(o3));
            }
        }
    }
}

// ---------------------------------------------------------------------------
// Deformable attention sampling (fp32 value, fp16 offlog) -> fp16 out.
// row0: global row offset of this launch's first (b,q).
// ---------------------------------------------------------------------------
__global__ __launch_bounds__(256)
void deform_kernel(const float* __restrict__ value,
                   const __half* __restrict__ offlog, int row0)
{
    const int bq   = row0 + blockIdx.x;
    const int q    = bq % Q_;
    const int b    = bq / Q_;
    const int h    = threadIdx.x >> 5;
    const int lane = threadIdx.x & 31;
    const unsigned FULL = 0xFFFFFFFFu;

    float logit = __half2float(offlog[(size_t)bq * 384 + 256 + h * 16 + (lane & 15)]);
    float mx = logit;
#pragma unroll
    for (int s = 8; s; s >>= 1) mx = fmaxf(mx, __shfl_xor_sync(FULL, mx, s));
    float e = expf(logit - mx);
    float sm = e;
#pragma unroll
    for (int s = 8; s; s >>= 1) sm += __shfl_xor_sync(FULL, sm, s);
    float aw = e / sm;

    float offv = __half2float(offlog[(size_t)bq * 384 + h * 32 + lane]);
    const float rx = d_ref[q * 2 + 0];
    const float ry = d_ref[q * 2 + 1];

    float acc = 0.f;
    const float* vb = value + (size_t)b * Q_ * C_ + h * DH_ + lane;

#pragma unroll
    for (int l = 0; l < NL_; l++) {
        const int   W  = c_lvl_w[l], H = c_lvl_h[l], st = c_lvl_start[l];
        const float fw = (float)W, fh = (float)H;
        const float iw = 1.f / fw, ih = 1.f / fh;
#pragma unroll
        for (int p = 0; p < NP_; p++) {
            const int j = l * NP_ + p;
            float ox  = __shfl_sync(FULL, offv, 2 * j);
            float oy  = __shfl_sync(FULL, offv, 2 * j + 1);
            float wj  = __shfl_sync(FULL, aw,   j);

            float x = (rx + ox * iw) * fw - 0.5f;
            float y = (ry + oy * ih) * fh - 0.5f;
            float x0f = floorf(x), y0f = floorf(y);
            int   x0  = (int)x0f,  y0  = (int)y0f;
            float fx = x - x0f, fy = y - y0f;
            float s = 0.f;

            bool vx0 = (x0 >= 0)     && (x0 < W);
            bool vx1 = (x0 + 1 >= 0) && (x0 + 1 < W);
            if (y0 >= 0 && y0 < H) {
                const float* rp = vb + (size_t)(st + y0 * W) * C_;
                float wy = 1.f - fy;
                if (vx0) s += wy * (1.f - fx) * rp[(size_t)x0 * C_];
                if (vx1) s += wy * fx         * rp[(size_t)(x0 + 1) * C_];
            }
            if (y0 + 1 >= 0 && y0 + 1 < H) {
                const float* rp = vb + (size_t)(st + (y0 + 1) * W) * C_;
                if (vx0) s += fy * (1.f - fx) * rp[(size_t)x0 * C_];
                if (vx1) s += fy * fx         * rp[(size_t)(x0 + 1) * C_];
            }
            acc = fmaf(wj, s, acc);
        }
    }
    d_ah[(size_t)bq * C_ + h * DH_ + lane] = __float2half_rn(acc);
}

// ---------------------------------------------------------------------------
// Fused residual-add + LayerNorm (vectorized): 4 rows per 256-thread block,
// 64 threads/row, float4/H4 per thread. y is fp16. row0 = global row offset.
// ---------------------------------------------------------------------------
template<bool WRITE_Q>
__global__ __launch_bounds__(256)
void add_ln_kernel(float* __restrict__ x, const __half* __restrict__ y,
                   const float* __restrict__ g, const float* __restrict__ b,
                   int row0)
{
    const int sub = threadIdx.x >> 6;          // row within block (0..3)
    const int t   = threadIdx.x & 63;          // 0..63
    const int row = row0 + blockIdx.x * 4 + sub;
    const size_t base = (size_t)row * C_ + t * 4;
    const unsigned FULL = 0xFFFFFFFFu;

    float4 xv = *(const float4*)&x[base];
    H4 yh = *(const H4*)&y[base];
    float2 y0 = __half22float2(yh.a);
    float2 y1 = __half22float2(yh.b);
    float4 v  = make_float4(xv.x + y0.x, xv.y + y0.y, xv.z + y1.x, xv.w + y1.y);

    float s1 = v.x + v.y + v.z + v.w;
    float s2 = v.x * v.x + v.y * v.y + v.z * v.z + v.w * v.w;
#pragma unroll
    for (int o = 16; o; o >>= 1) {
        s1 += __shfl_xor_sync(FULL, s1, o);
        s2 += __shfl_xor_sync(FULL, s2, o);
    }
    __shared__ float sh1[8], sh2[8];
    const int w = threadIdx.x >> 5, lane = threadIdx.x & 31;
    if (lane == 0) { sh1[w] = s1; sh2[w] = s2; }
    __syncthreads();
    float tot1 = sh1[2 * sub] + sh1[2 * sub + 1];
    float tot2 = sh2[2 * sub] + sh2[2 * sub + 1];
    float mean = tot1 * (1.f / C_);
    float var  = tot2 * (1.f / C_) - mean * mean;
    float rs   = rsqrtf(var + 1e-5f);

    float4 gg = *(const float4*)&g[t * 4];
    float4 bb = *(const float4*)&b[t * 4];
    float4 o;
    o.x = (v.x - mean) * rs * gg.x + bb.x;
    o.y = (v.y - mean) * rs * gg.y + bb.y;
    o.z = (v.z - mean) * rs * gg.z + bb.z;
    o.w = (v.w - mean) * rs * gg.w + bb.w;
    *(float4*)&x[base] = o;

    *(H4*)&d_xh[base] = rn4(o.x, o.y, o.z, o.w);
    if (WRITE_Q) {
        float4 pv = *(const float4*)&d_pos[base];
        *(H4*)&d_qh[base] = rn4(o.x + pv.x, o.y + pv.y, o.z + pv.z, o.w + pv.w);
    }
}

// ---------------------------------------------------------------------------
// Launch
// ---------------------------------------------------------------------------
extern "C" void kernel_launch(void* const* d_in, const int* in_sizes, int n_in,
                              void* d_out, int out_size)
{
    const float* src   = (const float*)d_in[0];
    const float* posf  = (const float*)d_in[1];
    const float* lemb  = (const float*)d_in[2];
    const float* Wsamp = (const float*)d_in[3];
    const float* bsamp = (const float*)d_in[4];
    const float* Wattn = (const float*)d_in[5];
    const float* battn = (const float*)d_in[6];
    const float* Wval  = (const float*)d_in[7];
    const float* bval  = (const float*)d_in[8];
    const float* Wout  = (const float*)d_in[9];
    const float* bout  = (const float*)d_in[10];
    const float* g1    = (const float*)d_in[11];
    const float* b1    = (const float*)d_in[12];
    const float* Wfc1  = (const float*)d_in[13];
    const float* bfc1  = (const float*)d_in[14];
    const float* Wfc2  = (const float*)d_in[15];
    const float* bfc2  = (const float*)d_in[16];
    const float* g2    = (const float*)d_in[17];
    const float* b2    = (const float*)d_in[18];

    float* x = (float*)d_out;

    // aux streams + events (created once; host-side only)
    static cudaStream_t s_aux[NCHUNK_ - 1] = {};
    static cudaEvent_t  ev_fork = nullptr;
    static cudaEvent_t  ev_join[NCHUNK_ - 1] = {};
    if (s_aux[0] == nullptr) {
        for (int i = 0; i < NCHUNK_ - 1; i++) {
            cudaStreamCreateWithFlags(&s_aux[i], cudaStreamNonBlocking);
            cudaEventCreateWithFlags(&ev_join[i], cudaEventDisableTiming);
        }
        cudaEventCreateWithFlags(&ev_fork, cudaEventDisableTiming);
    }

    static const int SMEM_DYN = 98304;   // 3 stages x 32768
    cudaFuncSetAttribute(hgemm_kernel<false, true,  false>,
                         cudaFuncAttributeMaxDynamicSharedMemorySize, SMEM_DYN);
    cudaFuncSetAttribute(hgemm_kernel<false, false, true>,
                         cudaFuncAttributeMaxDynamicSharedMemorySize, SMEM_DYN);
    cudaFuncSetAttribute(hgemm_kernel<true,  false, true>,
                         cudaFuncAttributeMaxDynamicSharedMemorySize, SMEM_DYN);

    float *p_val, *p_bsa;
    __half *p_ol, *p_tmph, *p_xh, *p_qh, *p_ah, *p_hh, *p_wh;
    cudaGetSymbolAddress((void**)&p_val,  d_value);
    cudaGetSymbolAddress((void**)&p_ol,   d_offlog);
    cudaGetSymbolAddress((void**)&p_bsa,  d_bsa);
    cudaGetSymbolAddress((void**)&p_tmph, d_tmph);
    cudaGetSymbolAddress((void**)&p_xh, d_xh);
    cudaGetSymbolAddress((void**)&p_qh, d_qh);
    cudaGetSymbolAddress((void**)&p_ah, d_ah);
    cudaGetSymbolAddress((void**)&p_hh, d_hh);
    cudaGetSymbolAddress((void**)&p_wh, d_wh);

    {
        size_t n4 = (size_t)M_ * C_ / 4;
        // setup fork: wsplit on s_aux[0], rest on main
        cudaEventRecord(ev_fork, 0);
        cudaStreamWaitEvent(s_aux[0], ev_fork, 0);
        wsplit_kernel<<<dim3(32, 32, 36), dim3(32, 8), 0, s_aux[0]>>>(
            Wval, Wsamp, Wattn, Wout, Wfc1, Wfc2);
        ref_kernel<<<(Q_ + 255) / 256, 256>>>();
        bias_pack_kernel<<<(NLAYERS_ * 384 + 255) / 256, 256>>>(bsamp, battn);
        init_kernel<<<(unsigned)((n4 + 255) / 256), 256>>>(src, posf, lemb, x);
    }

    // main must also wait for wsplit (weights used by all chains)
    cudaEventRecord(ev_join[0], s_aux[0]);
    cudaStreamWaitEvent(0, ev_join[0], 0);
    // fork NCHUNK_ independent batch-pair chains
    cudaEventRecord(ev_fork, 0);
    for (int i = 0; i < NCHUNK_ - 1; i++)
        cudaStreamWaitEvent(s_aux[i], ev_fork, 0);

    const int TILES = MQ_ / 128;              // 85
    const dim3 gN256(2, TILES);
    const dim3 gN384(3, TILES);
    const dim3 gN1024(8, TILES);

    for (int ch = 0; ch < NCHUNK_; ch++) {
        cudaStream_t st = (ch == 0) ? (cudaStream_t)0 : s_aux[ch - 1];
        const int r0 = ch * MQ_;

        for (int i = 0; i < NLAYERS_; i++) {
            const size_t wb = (size_t)i * W_LAYER;

            // value = x @ Wv + bv (fp32 out)
            hgemm_kernel<false, true, false><<<gN256, 128, SMEM_DYN, st>>>(
                p_xh + (size_t)r0 * 256, p_wh + wb + OFF_WV,
                bval + i * C_, p_val + (size_t)r0 * 256, nullptr,
                MQ_, 256, 256);
            // [off | logits] = q @ [Ws ; Wa] + [bs ; ba] -> fp16
            hgemm_kernel<false, false, true><<<gN384, 128, SMEM_DYN, st>>>(
                p_qh + (size_t)r0 * 256, p_wh + wb + OFF_WSA,
                p_bsa + i * 384, nullptr, p_ol + (size_t)r0 * 384,
                MQ_, 384, 256);
            // deformable sampling -> ah (fp16)
            deform_kernel<<<MQ_, 256, 0, st>>>(p_val, p_ol, r0);
            // attn = samp @ Wo + bo -> tmph (fp16)
            hgemm_kernel<false, false, true><<<gN256, 128, SMEM_DYN, st>>>(
                p_ah + (size_t)r0 * 256, p_wh + wb + OFF_WO,
                bout + i * C_, nullptr, p_tmph + (size_t)r0 * 256,
                MQ_, 256, 256);
            // x = LN(x + attn)
            add_ln_kernel<false><<<MQ_ / 4, 256, 0, st>>>(
                x, p_tmph, g1 + i * C_, b1 + i * C_, r0);
            // hid = relu(x @ W1 + b1) -> hh (fp16)
            hgemm_kernel<true, false, true><<<gN1024, 128, SMEM_DYN, st>>>(
                p_xh + (size_t)r0 * 256, p_wh + wb + OFF_W1,
                bfc1 + i * FFN_, nullptr, p_hh + (size_t)r0 * 1024,
                MQ_, 1024, 256);
            // tmp = hid @ W2 + b2 -> tmph (fp16)
            hgemm_kernel<false, false, true><<<gN256, 128, SMEM_DYN, st>>>(
                p_hh + (size_t)r0 * 1024, p_wh + wb + OFF_W2,
                bfc2 + i * C_, nullptr, p_tmph + (size_t)r0 * 256,
                MQ_, 256, 1024);
            // x = LN(x + ffn), also produce next-layer query fp16
            add_ln_kernel<true><<<MQ_ / 4, 256, 0, st>>>(
                x, p_tmph, g2 + i * C_, b2 + i * C_, r0);
        }
    }

    // join aux chains back into the capture stream
    for (int i = 0; i < NCHUNK_ - 1; i++) {
        cudaEventRecord(ev_join[i], s_aux[i]);
        cudaStreamWaitEvent(0, ev_join[i], 0);
    }
}